// round 13
// baseline (speedup 1.0000x reference)
#include <cuda_runtime.h>
#include <cuda_bf16.h>
#include <math.h>
#include <cstdint>

#define NROWS 256
#define DDIM  4096
#define CIN   8192
#define HID   4096
#define Y0DIM 512
#define QLAG  64
#define NLAG  129
#define SPLITK 8

// ---------------- scratch (device globals; no allocations allowed) ----------------
__device__ float g_w[NLAG];
__device__ float g_covpart[SPLITK * NROWS * NROWS];

// packed operands: per 32-k chunk, per row: 128B = [hi bf16 x32 | lo bf16 x32]
__device__ __align__(128) char g_Wp1[(size_t)HID * CIN * 4];     // fc1_w packed
__device__ __align__(128) char g_Wp2[(size_t)HID * HID * 4];     // fc2_w packed
__device__ __align__(128) char g_Wp3[(size_t)HID * HID * 4];     // fc3_w packed
__device__ __align__(128) char g_Pp [(size_t)Y0DIM * NROWS * 4]; // proj packed
__device__ __align__(128) char g_Zp [(size_t)NROWS * CIN * 4];   // [X | cov@X] packed
__device__ __align__(128) char g_o1p[(size_t)NROWS * HID * 4];
__device__ __align__(128) char g_o2p[(size_t)NROWS * HID * 4];
__device__ __align__(128) char g_o3tp[(size_t)HID * NROWS * 4];  // fc3 out transposed packed
__device__ __align__(128) char g_Xtp[(size_t)DDIM * NROWS * 4];  // X^T packed
__device__ __align__(128) char g_Cp [(size_t)NROWS * NROWS * 4]; // cov packed
__device__ __align__(128) char g_Xcp[(size_t)NROWS * DDIM * 4];  // centered X packed
__device__ __align__(128) char g_Yp [(size_t)NROWS * DDIM * 4];  // FIR output packed

__device__ __forceinline__ float gelu_f(float x) {
    return 0.5f * x * (1.0f + erff(x * 0.70710678118654752440f));
}
__device__ __forceinline__ uint32_t smem_u32(const void* p) {
    uint32_t a;
    asm("{ .reg .u64 t; cvta.to.shared.u64 t, %1; cvt.u32.u64 %0, t; }" : "=r"(a) : "l"(p));
    return a;
}
__device__ __forceinline__ void ldsm4(uint32_t* r, uint32_t addr) {
    asm volatile("ldmatrix.sync.aligned.m8n8.x4.shared.b16 {%0,%1,%2,%3}, [%4];"
        : "=r"(r[0]), "=r"(r[1]), "=r"(r[2]), "=r"(r[3]) : "r"(addr));
}
__device__ __forceinline__ void mma16816(float* c, const uint32_t* a, const uint32_t* b) {
    asm volatile(
        "mma.sync.aligned.m16n8k16.row.col.f32.bf16.bf16.f32 "
        "{%0,%1,%2,%3}, {%4,%5,%6,%7}, {%8,%9}, {%0,%1,%2,%3};"
        : "+f"(c[0]), "+f"(c[1]), "+f"(c[2]), "+f"(c[3])
        : "r"(a[0]), "r"(a[1]), "r"(a[2]), "r"(a[3]), "r"(b[0]), "r"(b[1]));
}
__device__ __forceinline__ uint32_t pack_bf(float a, float b) {
    __nv_bfloat162 t;
    t.x = __float2bfloat16(a);
    t.y = __float2bfloat16(b);
    return *reinterpret_cast<uint32_t*>(&t);
}
__device__ __forceinline__ float bf_hi(float x) {
    return __bfloat162float(__float2bfloat16(x));
}
__device__ __forceinline__ uint32_t swz(uint32_t off) {
    return off ^ (((off >> 7) & 7) << 4);
}
__device__ __forceinline__ void cp16(uint32_t d, const void* s) {
    asm volatile("cp.async.cg.shared.global [%0], [%1], 16;" :: "r"(d), "l"(s) : "memory");
}
#define CP_COMMIT() asm volatile("cp.async.commit_group;" ::: "memory")
#define CP_WAIT2()  asm volatile("cp.async.wait_group 2;" ::: "memory")
#define CP_WAIT1()  asm volatile("cp.async.wait_group 1;" ::: "memory")
#define CP_WAIT0()  asm volatile("cp.async.wait_group 0;" ::: "memory")

// pack 8 fp32 -> hi uint4 (8 bf16) + lo uint4
__device__ __forceinline__ void pack8(const float* f, uint4& hi, uint4& lo) {
    float h[8];
    #pragma unroll
    for (int u = 0; u < 8; ++u) h[u] = bf_hi(f[u]);
    hi = make_uint4(pack_bf(h[0], h[1]), pack_bf(h[2], h[3]),
                    pack_bf(h[4], h[5]), pack_bf(h[6], h[7]));
    lo = make_uint4(pack_bf(f[0]-h[0], f[1]-h[1]), pack_bf(f[2]-h[2], f[3]-h[3]),
                    pack_bf(f[4]-h[4], f[5]-h[5]), pack_bf(f[6]-h[6], f[7]-h[7]));
}

// ====================== pipelined HMMA bf16 3-split NT GEMM ======================
// Operands pre-packed. BM=64, BN=128. Superstage = 2 chunks (64 k), 4 slots,
// wait depth 2 (two superstage loads in flight during compute).
// OMODE: 0 = fp32 row-major out; 1 = packed out (kbase = k offset);
//        2 = packed transposed out; 3 = fp32 out + blockIdx.z partial (kbase = zstride)
#define NSS 4
#define A_SS 16384                       // 2 chunks x 8KB
#define B_SS 32768                       // 2 chunks x 16KB
#define GEMM_SMEM (NSS * (A_SS + B_SS))  // 192KB

template <int OMODE, bool BIAS, bool GELU, bool SPLITZ>
__global__ void __launch_bounds__(256) gemm_k(
    const char* __restrict__ Ap, const char* __restrict__ Bp,
    void* __restrict__ Cout, const float* __restrict__ bias,
    int NC, int RA, int RB, int ldOut, int kbase)
{
    extern __shared__ __align__(128) char dsm[];
    const uint32_t sb = smem_u32(dsm);
    const int tid = threadIdx.x;
    const int lane = tid & 31, wid = tid >> 5;
    const int warp_m = wid >> 2, warp_n = wid & 3;
    const int m0 = blockIdx.y * 64, n0 = blockIdx.x * 128;
    const int zb = SPLITZ ? blockIdx.z * NC : 0;

    const uint32_t dA0 = swz(tid * 16), dA1 = swz((tid + 256) * 16);
    uint32_t dB[4];
    #pragma unroll
    for (int j = 0; j < 4; ++j) dB[j] = swz((tid + 256 * j) * 16);

    // ldmatrix offsets within one 8KB(A)/16KB(B) chunk: [plane][kstep][frag]
    uint32_t aoff[2][2][2], boff[2][2][2];
    #pragma unroll
    for (int p = 0; p < 2; ++p)
        #pragma unroll
        for (int s = 0; s < 2; ++s)
            #pragma unroll
            for (int f = 0; f < 2; ++f) {
                int rowA = warp_m * 32 + f * 16 + (lane & 15);
                aoff[p][s][f] = swz((uint32_t)rowA * 128 + p * 64 + s * 32 + ((lane >> 4) << 4));
                int rowB = warp_n * 32 + f * 16 + (((lane >> 4) & 1) << 3) + (lane & 7);
                boff[p][s][f] = swz((uint32_t)rowB * 128 + p * 64 + s * 32 + (((lane >> 3) & 1) << 4));
            }

    float acc[2][4][4];
    #pragma unroll
    for (int i = 0; i < 2; ++i)
        #pragma unroll
        for (int j = 0; j < 4; ++j)
            #pragma unroll
            for (int r = 0; r < 4; ++r) acc[i][j][r] = 0.f;

    const int NSC = NC >> 1;             // superchunks (NC always even)

    auto issue_ss = [&](int isc, int slot) {
        #pragma unroll
        for (int c = 0; c < 2; ++c) {
            int ic = 2 * isc + c;
            const char* a = Ap + (((size_t)(zb + ic) * RA + m0) << 7);
            const char* b = Bp + (((size_t)(zb + ic) * RB + n0) << 7);
            uint32_t sA = sb + slot * A_SS + c * 8192;
            uint32_t sB = sb + NSS * A_SS + slot * B_SS + c * 16384;
            cp16(sA + dA0, a + (size_t)tid * 16);
            cp16(sA + dA1, a + (size_t)(tid + 256) * 16);
            #pragma unroll
            for (int j = 0; j < 4; ++j) cp16(sB + dB[j], b + (size_t)(tid + 256 * j) * 16);
        }
        CP_COMMIT();
    };

    issue_ss(0, 0);
    if (NSC > 1) issue_ss(1, 1);
    if (NSC > 2) issue_ss(2, 2);

    for (int i = 0; i < NSC; ++i) {
        int pend = NSC - 1 - i;          // groups issued after group i (pre-issue)
        if (pend >= 2) CP_WAIT2(); else if (pend == 1) CP_WAIT1(); else CP_WAIT0();
        __syncthreads();
        if (i + 3 < NSC) issue_ss(i + 3, (i + 3) & 3);

        const int slot = i & 3;
        #pragma unroll
        for (int c = 0; c < 2; ++c) {
            const uint32_t baseA = sb + slot * A_SS + c * 8192;
            const uint32_t baseB = sb + NSS * A_SS + slot * B_SS + c * 16384;
            #pragma unroll
            for (int s = 0; s < 2; ++s) {
                uint32_t ah[2][4], al[2][4], bh[4][2], bl[4][2];
                #pragma unroll
                for (int f = 0; f < 2; ++f) {
                    ldsm4(ah[f], baseA + aoff[0][s][f]);
                    ldsm4(al[f], baseA + aoff[1][s][f]);
                }
                #pragma unroll
                for (int pr = 0; pr < 2; ++pr) {
                    uint32_t t[4];
                    ldsm4(t, baseB + boff[0][s][pr]);
                    bh[2*pr][0]=t[0]; bh[2*pr][1]=t[1]; bh[2*pr+1][0]=t[2]; bh[2*pr+1][1]=t[3];
                    ldsm4(t, baseB + boff[1][s][pr]);
                    bl[2*pr][0]=t[0]; bl[2*pr][1]=t[1]; bl[2*pr+1][0]=t[2]; bl[2*pr+1][1]=t[3];
                }
                #pragma unroll
                for (int f = 0; f < 2; ++f)
                    #pragma unroll
                    for (int j = 0; j < 4; ++j) {
                        mma16816(acc[f][j], ah[f], bh[j]);   // hh
                        mma16816(acc[f][j], al[f], bh[j]);   // lh
                        mma16816(acc[f][j], ah[f], bl[j]);   // hl
                    }
            }
        }
    }
    __syncthreads();

    // ---- stage accumulators into smem ----
    float* so = (float*)dsm;                     // 64 x 129
    #pragma unroll
    for (int i2 = 0; i2 < 2; ++i2)
        #pragma unroll
        for (int j = 0; j < 4; ++j)
            #pragma unroll
            for (int r = 0; r < 4; ++r) {
                int row = warp_m * 32 + i2 * 16 + (lane >> 2) + ((r >> 1) << 3);
                int col = warp_n * 32 + j * 8 + ((lane & 3) << 1) + (r & 1);
                so[row * 129 + col] = acc[i2][j][r];
            }
    __syncthreads();

    if (OMODE == 0 || OMODE == 3) {
        float* C = (float*)Cout + (SPLITZ ? (size_t)blockIdx.z * (size_t)kbase : 0);
        #pragma unroll
        for (int it = 0; it < 8; ++it) {
            int idx = tid + 256 * it;
            int row = idx >> 5, q = idx & 31;
            float o[4];
            #pragma unroll
            for (int u = 0; u < 4; ++u) {
                float v = so[row * 129 + q * 4 + u];
                if (BIAS) v += __ldg(bias + n0 + q * 4 + u);
                if (GELU) v = gelu_f(v);
                o[u] = v;
            }
            *(float4*)(C + (size_t)(m0 + row) * ldOut + n0 + q * 4) = *(const float4*)o;
        }
    } else if (OMODE == 1) {
        char* dst = (char*)Cout;
        #pragma unroll
        for (int it = 0; it < 4; ++it) {
            int task = tid + 256 * it;               // 1024 tasks: 64 m x 16 c-groups
            int m = task >> 4, c = (task & 15) * 8;
            float v[8];
            #pragma unroll
            for (int u = 0; u < 8; ++u) {
                float x = so[m * 129 + c + u];
                if (BIAS) x += __ldg(bias + n0 + c + u);
                if (GELU) x = gelu_f(x);
                v[u] = x;
            }
            uint4 hi, lo;
            pack8(v, hi, lo);
            int kk = kbase + n0 + c;
            size_t base = (((size_t)(kk >> 5) * ldOut + m0 + m) << 7) + ((kk & 31) >> 3) * 16;
            *(uint4*)(dst + base) = hi;
            *(uint4*)(dst + base + 64) = lo;
        }
    } else {
        // packed transposed: out rows = n-global, k = m-global
        char* dst = (char*)Cout;
        int h = tid >> 7, n = tid & 127;
        float bv = BIAS ? __ldg(bias + n0 + n) : 0.f;
        float v[32];
        #pragma unroll
        for (int i2 = 0; i2 < 32; ++i2) {
            float x = so[(h * 32 + i2) * 129 + n] + bv;
            if (GELU) x = gelu_f(x);
            v[i2] = x;
        }
        size_t base = (((size_t)((m0 >> 5) + h) * ldOut + n0 + n) << 7);
        #pragma unroll
        for (int q = 0; q < 4; ++q) {
            uint4 hi, lo;
            pack8(v + 8 * q, hi, lo);
            *(uint4*)(dst + base + q * 16) = hi;
            *(uint4*)(dst + base + 64 + q * 16) = lo;
        }
    }
}

// ---------------- generic fp32 -> packed converter (R6 proven) ----------------
__global__ void pack_kernel(const float* __restrict__ src, char* __restrict__ dst,
                            int R, int K, int total) {
    int idx = blockIdx.x * 256 + threadIdx.x;
    if (idx >= total) return;
    int kg = K >> 3;
    int r = idx / kg;
    int koff = (idx - r * kg) << 3;
    float f[8];
    *(float4*)f       = *(const float4*)(src + (size_t)r * K + koff);
    *(float4*)(f + 4) = *(const float4*)(src + (size_t)r * K + koff + 4);
    uint4 hi, lo;
    pack8(f, hi, lo);
    size_t base = (((size_t)(koff >> 5) * R + r) << 7) + ((koff & 31) >> 3) * 16;
    *(uint4*)(dst + base) = hi;
    *(uint4*)(dst + base + 64) = lo;
}

// ---------------- 1) weight net ----------------
__global__ void weight_kernel(const float* __restrict__ w1, const float* __restrict__ b1,
                              const float* __restrict__ w2, const float* __restrict__ b2) {
    int l = threadIdx.x;
    if (l >= NLAG) return;
    float lag = (float)(l - QLAG);
    float acc = b2[0];
    #pragma unroll 8
    for (int j = 0; j < 64; ++j) acc += gelu_f(lag * w1[j] + b1[j]) * w2[j];
    g_w[l] = acc;
}

// ---------------- 2) fused center + FIR + pack: one X-row read ----------------
// Per block = one row r. Emits: Zp (raw X packed), Xcp (centered packed),
// Yp (FIR output packed). FIR math identical to R6 fir_kernel.
__global__ void center_fir_kernel(const float* __restrict__ X, char* __restrict__ Zp,
                                  char* __restrict__ Xcp, char* __restrict__ Yp) {
    __shared__ float sbuf[DDIM + 2 * QLAG];
    __shared__ float ws[NLAG];
    __shared__ float red[256];
    int r = blockIdx.x, tid = threadIdx.x;
    if (tid < NLAG) ws[tid] = g_w[tid];
    if (tid < QLAG) { sbuf[tid] = 0.f; sbuf[DDIM + QLAG + tid] = 0.f; }

    const float* xr = X + (size_t)r * DDIM;
    float f0[8], f1[8];
    int k0 = tid * 8, k1 = 2048 + tid * 8;
    *(float4*)f0       = *(const float4*)(xr + k0);
    *(float4*)(f0 + 4) = *(const float4*)(xr + k0 + 4);
    *(float4*)f1       = *(const float4*)(xr + k1);
    *(float4*)(f1 + 4) = *(const float4*)(xr + k1 + 4);
    float s = 0.f;
    #pragma unroll
    for (int u = 0; u < 8; ++u) s += f0[u] + f1[u];
    red[tid] = s; __syncthreads();
    for (int off = 128; off > 0; off >>= 1) {
        if (tid < off) red[tid] += red[tid + off];
        __syncthreads();
    }
    float mean = red[0] * (1.0f / DDIM);

    uint4 hi, lo;
    size_t b0 = (((size_t)(k0 >> 5) * NROWS + r) << 7) + ((k0 & 31) >> 3) * 16;
    size_t b1 = (((size_t)(k1 >> 5) * NROWS + r) << 7) + ((k1 & 31) >> 3) * 16;
    pack8(f0, hi, lo);
    *(uint4*)(Zp + b0) = hi; *(uint4*)(Zp + b0 + 64) = lo;
    pack8(f1, hi, lo);
    *(uint4*)(Zp + b1) = hi; *(uint4*)(Zp + b1 + 64) = lo;

    #pragma unroll
    for (int u = 0; u < 8; ++u) { f0[u] -= mean; f1[u] -= mean; }
    pack8(f0, hi, lo);
    *(uint4*)(Xcp + b0) = hi; *(uint4*)(Xcp + b0 + 64) = lo;
    pack8(f1, hi, lo);
    *(uint4*)(Xcp + b1) = hi; *(uint4*)(Xcp + b1 + 64) = lo;

    // centered row into smem (with apron) for FIR
    *(float4*)(&sbuf[QLAG + k0])     = *(float4*)f0;
    *(float4*)(&sbuf[QLAG + k0 + 4]) = *(float4*)(f0 + 4);
    *(float4*)(&sbuf[QLAG + k1])     = *(float4*)f1;
    *(float4*)(&sbuf[QLAG + k1 + 4]) = *(float4*)(f1 + 4);
    __syncthreads();

    // FIR (identical to R6): acc[s] = Y[tid + 256*s]
    float acc[16];
    #pragma unroll
    for (int q = 0; q < 16; ++q) acc[q] = 0.f;
    for (int i = 0; i < NLAG; ++i) {
        float wv = ws[i];
        #pragma unroll
        for (int q = 0; q < 16; ++q) acc[q] += wv * sbuf[tid + 256 * q + i];
    }
    __syncthreads();
    // stage FIR output in smem (overwrite input), then pack 16 consecutive / thread
    #pragma unroll
    for (int q = 0; q < 16; ++q) sbuf[tid + 256 * q] = acc[q];
    __syncthreads();

    int t0 = tid * 16;
    float v[16];
    #pragma unroll
    for (int u = 0; u < 16; ++u) v[u] = sbuf[t0 + u];
    #pragma unroll
    for (int g = 0; g < 2; ++g) {
        int koff = t0 + 8 * g;
        size_t base = (((size_t)(koff >> 5) * NROWS + r) << 7) + ((koff & 31) >> 3) * 16;
        pack8(v + 8 * g, hi, lo);
        *(uint4*)(Yp + base) = hi;
        *(uint4*)(Yp + base + 64) = lo;
    }
}

// ---------------- transpose X -> packed Xt [DDIM rows, K=NROWS] ----------------
__global__ void transpose_kernel(const float* __restrict__ X, char* __restrict__ XTp) {
    __shared__ float t[32][33];
    int bx = blockIdx.x * 32;
    int by = blockIdx.y * 32;
    int x = threadIdx.x, y = threadIdx.y;
    #pragma unroll
    for (int j = 0; j < 32; j += 8)
        t[y + j][x] = X[(size_t)(by + y + j) * DDIM + bx + x];
    __syncthreads();
    int tt = y * 32 + x;
    if (tt < 128) {
        int rr = tt >> 2, grp = tt & 3;
        float v[8];
        #pragma unroll
        for (int u = 0; u < 8; ++u) v[u] = t[grp * 8 + u][rr];
        uint4 hi, lo;
        pack8(v, hi, lo);
        size_t base = (((size_t)(by >> 5) * DDIM + bx + rr) << 7) + grp * 16;
        *(uint4*)(XTp + base) = hi;
        *(uint4*)(XTp + base + 64) = lo;
    }
}

// cov reduce + pack: 8192 tasks (256 rows x 32 groups of 8)
__global__ void cov_reduce(char* __restrict__ Cp) {
    int idx = blockIdx.x * 256 + threadIdx.x;
    int r = idx >> 5;
    int cg = (idx & 31) << 3;
    float v[8];
    #pragma unroll
    for (int u = 0; u < 8; ++u) v[u] = 0.f;
    #pragma unroll
    for (int z = 0; z < SPLITK; ++z) {
        const float* p = g_covpart + (size_t)z * NROWS * NROWS + (size_t)r * NROWS + cg;
        float4 a = *(const float4*)p, b = *(const float4*)(p + 4);
        v[0]+=a.x; v[1]+=a.y; v[2]+=a.z; v[3]+=a.w;
        v[4]+=b.x; v[5]+=b.y; v[6]+=b.z; v[7]+=b.w;
    }
    #pragma unroll
    for (int u = 0; u < 8; ++u) v[u] *= (1.0f / DDIM);
    uint4 hi, lo;
    pack8(v, hi, lo);
    size_t base = (((size_t)(cg >> 5) * NROWS + r) << 7) + ((cg & 31) >> 3) * 16;
    *(uint4*)(Cp + base) = hi;
    *(uint4*)(Cp + base + 64) = lo;
}

// ---------------- launch (single stream) ----------------
extern "C" void kernel_launch(void* const* d_in, const int* in_sizes, int n_in,
                              void* d_out, int out_size) {
    const float* X     = (const float*)d_in[0];
    const float* wn_w1 = (const float*)d_in[1];
    const float* wn_b1 = (const float*)d_in[2];
    const float* wn_w2 = (const float*)d_in[3];
    const float* wn_b2 = (const float*)d_in[4];
    const float* fc1_w = (const float*)d_in[5];
    const float* fc1_b = (const float*)d_in[6];
    const float* fc2_w = (const float*)d_in[7];
    const float* fc2_b = (const float*)d_in[8];
    const float* fc3_w = (const float*)d_in[9];
    const float* fc3_b = (const float*)d_in[10];
    const float* proj  = (const float*)d_in[11];
    float* out = (float*)d_out;

    char *pWp1, *pWp2, *pWp3, *pPp, *pZp, *po1p, *po2p, *po3tp, *pXtp, *pCp, *pXcp, *pYp;
    float *pcovp;
    cudaGetSymbolAddress((void**)&pWp1,  g_Wp1);
    cudaGetSymbolAddress((void**)&pWp2,  g_Wp2);
    cudaGetSymbolAddress((void**)&pWp3,  g_Wp3);
    cudaGetSymbolAddress((void**)&pPp,   g_Pp);
    cudaGetSymbolAddress((void**)&pZp,   g_Zp);
    cudaGetSymbolAddress((void**)&po1p,  g_o1p);
    cudaGetSymbolAddress((void**)&po2p,  g_o2p);
    cudaGetSymbolAddress((void**)&po3tp, g_o3tp);
    cudaGetSymbolAddress((void**)&pXtp,  g_Xtp);
    cudaGetSymbolAddress((void**)&pCp,   g_Cp);
    cudaGetSymbolAddress((void**)&pXcp,  g_Xcp);
    cudaGetSymbolAddress((void**)&pYp,   g_Yp);
    cudaGetSymbolAddress((void**)&pcovp, g_covpart);

    cudaFuncSetAttribute(gemm_k<0, false, false, false>, cudaFuncAttributeMaxDynamicSharedMemorySize, GEMM_SMEM);
    cudaFuncSetAttribute(gemm_k<1, false, false, false>, cudaFuncAttributeMaxDynamicSharedMemorySize, GEMM_SMEM);
    cudaFuncSetAttribute(gemm_k<1, true,  true,  false>, cudaFuncAttributeMaxDynamicSharedMemorySize, GEMM_SMEM);
    cudaFuncSetAttribute(gemm_k<2, true,  false, false>, cudaFuncAttributeMaxDynamicSharedMemorySize, GEMM_SMEM);
    cudaFuncSetAttribute(gemm_k<3, false, false, true >, cudaFuncAttributeMaxDynamicSharedMemorySize, GEMM_SMEM);

    weight_kernel<<<1, NLAG>>>(wn_w1, wn_b1, wn_w2, wn_b2);
    center_fir_kernel<<<NROWS, 256>>>(X, pZp, pXcp, pYp);
    transpose_kernel<<<dim3(DDIM / 32, NROWS / 32), dim3(32, 8)>>>(X, pXtp);
    // cov partials: HMMA split-K over blockIdx.z (K-slice = 512 = 16 chunks)
    gemm_k<3, false, false, true><<<dim3(NROWS / 128, NROWS / 64, SPLITK), 256, GEMM_SMEM>>>(
        pXcp, pYp, pcovp, nullptr, (DDIM / SPLITK) / 32, NROWS, NROWS, NROWS, NROWS * NROWS);
    cov_reduce<<<32, 256>>>(pCp);

    // cov_inter = cov @ X -> Zp right half (packed, kbase=DDIM)
    gemm_k<1, false, false, false><<<dim3(DDIM / 128, NROWS / 64), 256, GEMM_SMEM>>>(
        pCp, pXtp, pZp, nullptr, NROWS / 32, NROWS, DDIM, NROWS, DDIM);

    // pack weights + proj
    {
        int t1 = HID * CIN / 8;
        pack_kernel<<<(t1 + 255) / 256, 256>>>(fc1_w, pWp1, HID, CIN, t1);
        int t2 = HID * HID / 8;
        pack_kernel<<<(t2 + 255) / 256, 256>>>(fc2_w, pWp2, HID, HID, t2);
        pack_kernel<<<(t2 + 255) / 256, 256>>>(fc3_w, pWp3, HID, HID, t2);
        int t3 = Y0DIM * NROWS / 8;
        pack_kernel<<<(t3 + 255) / 256, 256>>>(proj, pPp, Y0DIM, NROWS, t3);
    }

    // fc1: gelu(Z @ fc1_w^T + b) -> o1p
    gemm_k<1, true, true, false><<<dim3(HID / 128, NROWS / 64), 256, GEMM_SMEM>>>(
        pZp, pWp1, po1p, fc1_b, CIN / 32, NROWS, HID, NROWS, 0);
    // fc2: gelu(o1 @ fc2_w^T + b) -> o2p
    gemm_k<1, true, true, false><<<dim3(HID / 128, NROWS / 64), 256, GEMM_SMEM>>>(
        po1p, pWp2, po2p, fc2_b, HID / 32, NROWS, HID, NROWS, 0);
    // fc3: o2 @ fc3_w^T + b -> o3tp (packed transposed)
    gemm_k<2, true, false, false><<<dim3(HID / 128, NROWS / 64), 256, GEMM_SMEM>>>(
        po2p, pWp3, po3tp, fc3_b, HID / 32, NROWS, HID, HID, 0);
    // out = proj @ o3 (NT: A=projp, B=o3tp) -> fp32 out
    gemm_k<0, false, false, false><<<dim3(HID / 128, Y0DIM / 64), 256, GEMM_SMEM>>>(
        pPp, po3tp, out, nullptr, NROWS / 32, Y0DIM, HID, HID, 0);
}

// round 14
// speedup vs baseline: 1.0275x; 1.0275x over previous
#include <cuda_runtime.h>
#include <cuda_bf16.h>
#include <math.h>
#include <cstdint>

#define NROWS 256
#define DDIM  4096
#define CIN   8192
#define HID   4096
#define Y0DIM 512
#define QLAG  64
#define NLAG  129
#define SPLITK 16

// ---------------- scratch (device globals; no allocations allowed) ----------------
__device__ float g_w[NLAG];
__device__ float g_covpart[SPLITK * NROWS * NROWS];

// packed operands: per 32-k chunk, per row: 128B = [hi bf16 x32 | lo bf16 x32]
__device__ __align__(128) char g_Wp1[(size_t)HID * CIN * 4];     // fc1_w packed
__device__ __align__(128) char g_Wp2[(size_t)HID * HID * 4];     // fc2_w packed
__device__ __align__(128) char g_Wp3[(size_t)HID * HID * 4];     // fc3_w packed
__device__ __align__(128) char g_Pp [(size_t)Y0DIM * NROWS * 4]; // proj packed
__device__ __align__(128) char g_Zp [(size_t)NROWS * CIN * 4];   // [X | cov@X] packed
__device__ __align__(128) char g_o1p[(size_t)NROWS * HID * 4];
__device__ __align__(128) char g_o2p[(size_t)NROWS * HID * 4];
__device__ __align__(128) char g_o3tp[(size_t)HID * NROWS * 4];  // fc3 out transposed packed
__device__ __align__(128) char g_Xtp[(size_t)DDIM * NROWS * 4];  // X^T packed
__device__ __align__(128) char g_Cp [(size_t)NROWS * NROWS * 4]; // cov packed
__device__ __align__(128) char g_Xcp[(size_t)NROWS * DDIM * 4];  // centered X packed
__device__ __align__(128) char g_Yp [(size_t)NROWS * DDIM * 4];  // FIR output packed

__device__ __forceinline__ float gelu_f(float x) {
    return 0.5f * x * (1.0f + erff(x * 0.70710678118654752440f));
}
__device__ __forceinline__ uint32_t smem_u32(const void* p) {
    uint32_t a;
    asm("{ .reg .u64 t; cvta.to.shared.u64 t, %1; cvt.u32.u64 %0, t; }" : "=r"(a) : "l"(p));
    return a;
}
__device__ __forceinline__ void ldsm4(uint32_t* r, uint32_t addr) {
    asm volatile("ldmatrix.sync.aligned.m8n8.x4.shared.b16 {%0,%1,%2,%3}, [%4];"
        : "=r"(r[0]), "=r"(r[1]), "=r"(r[2]), "=r"(r[3]) : "r"(addr));
}
__device__ __forceinline__ void mma16816(float* c, const uint32_t* a, const uint32_t* b) {
    asm volatile(
        "mma.sync.aligned.m16n8k16.row.col.f32.bf16.bf16.f32 "
        "{%0,%1,%2,%3}, {%4,%5,%6,%7}, {%8,%9}, {%0,%1,%2,%3};"
        : "+f"(c[0]), "+f"(c[1]), "+f"(c[2]), "+f"(c[3])
        : "r"(a[0]), "r"(a[1]), "r"(a[2]), "r"(a[3]), "r"(b[0]), "r"(b[1]));
}
__device__ __forceinline__ uint32_t pack_bf(float a, float b) {
    __nv_bfloat162 t;
    t.x = __float2bfloat16(a);
    t.y = __float2bfloat16(b);
    return *reinterpret_cast<uint32_t*>(&t);
}
__device__ __forceinline__ float bf_hi(float x) {
    return __bfloat162float(__float2bfloat16(x));
}
__device__ __forceinline__ uint32_t swz(uint32_t off) {
    return off ^ (((off >> 7) & 7) << 4);
}
__device__ __forceinline__ void cp16(uint32_t d, const void* s) {
    asm volatile("cp.async.cg.shared.global [%0], [%1], 16;" :: "r"(d), "l"(s) : "memory");
}
#define CP_COMMIT() asm volatile("cp.async.commit_group;" ::: "memory")
#define CP_WAIT1()  asm volatile("cp.async.wait_group 1;" ::: "memory")
#define CP_WAIT0()  asm volatile("cp.async.wait_group 0;" ::: "memory")

// pack 8 fp32 -> hi uint4 (8 bf16) + lo uint4
__device__ __forceinline__ void pack8(const float* f, uint4& hi, uint4& lo) {
    float h[8];
    #pragma unroll
    for (int u = 0; u < 8; ++u) h[u] = bf_hi(f[u]);
    hi = make_uint4(pack_bf(h[0], h[1]), pack_bf(h[2], h[3]),
                    pack_bf(h[4], h[5]), pack_bf(h[6], h[7]));
    lo = make_uint4(pack_bf(f[0]-h[0], f[1]-h[1]), pack_bf(f[2]-h[2], f[3]-h[3]),
                    pack_bf(f[4]-h[4], f[5]-h[5]), pack_bf(f[6]-h[6], f[7]-h[7]));
}

// ====================== pipelined HMMA bf16 3-split NT GEMM (R12 proven) ======================
// Operands pre-packed. BM=64, BN=128. Superstage = 2 chunks (64 k), 3 slots, wait depth 1.
// OMODE: 0 = fp32 row-major out; 1 = packed out (kbase = k offset);
//        2 = packed transposed out; 3 = fp32 out + blockIdx.z partial (kbase = zstride)
#define NSS 3
#define A_SS 16384                       // 2 chunks x 8KB
#define B_SS 32768                       // 2 chunks x 16KB
#define GEMM_SMEM (NSS * (A_SS + B_SS))  // 144KB

template <int OMODE, bool BIAS, bool GELU, bool SPLITZ>
__global__ void __launch_bounds__(256) gemm_k(
    const char* __restrict__ Ap, const char* __restrict__ Bp,
    void* __restrict__ Cout, const float* __restrict__ bias,
    int NC, int RA, int RB, int ldOut, int kbase)
{
    extern __shared__ __align__(128) char dsm[];
    const uint32_t sb = smem_u32(dsm);
    const int tid = threadIdx.x;
    const int lane = tid & 31, wid = tid >> 5;
    const int warp_m = wid >> 2, warp_n = wid & 3;
    const int m0 = blockIdx.y * 64, n0 = blockIdx.x * 128;
    const int zb = SPLITZ ? blockIdx.z * NC : 0;

    const uint32_t dA0 = swz(tid * 16), dA1 = swz((tid + 256) * 16);
    uint32_t dB[4];
    #pragma unroll
    for (int j = 0; j < 4; ++j) dB[j] = swz((tid + 256 * j) * 16);

    // ldmatrix offsets within one 8KB(A)/16KB(B) chunk: [plane][kstep][frag]
    uint32_t aoff[2][2][2], boff[2][2][2];
    #pragma unroll
    for (int p = 0; p < 2; ++p)
        #pragma unroll
        for (int s = 0; s < 2; ++s)
            #pragma unroll
            for (int f = 0; f < 2; ++f) {
                int rowA = warp_m * 32 + f * 16 + (lane & 15);
                aoff[p][s][f] = swz((uint32_t)rowA * 128 + p * 64 + s * 32 + ((lane >> 4) << 4));
                int rowB = warp_n * 32 + f * 16 + (((lane >> 4) & 1) << 3) + (lane & 7);
                boff[p][s][f] = swz((uint32_t)rowB * 128 + p * 64 + s * 32 + (((lane >> 3) & 1) << 4));
            }

    float acc[2][4][4];
    #pragma unroll
    for (int i = 0; i < 2; ++i)
        #pragma unroll
        for (int j = 0; j < 4; ++j)
            #pragma unroll
            for (int r = 0; r < 4; ++r) acc[i][j][r] = 0.f;

    const int NSC = NC >> 1;             // superchunks (NC always even)

    auto issue_ss = [&](int isc, int slot) {
        #pragma unroll
        for (int c = 0; c < 2; ++c) {
            int ic = 2 * isc + c;
            const char* a = Ap + (((size_t)(zb + ic) * RA + m0) << 7);
            const char* b = Bp + (((size_t)(zb + ic) * RB + n0) << 7);
            uint32_t sA = sb + slot * A_SS + c * 8192;
            uint32_t sB = sb + NSS * A_SS + slot * B_SS + c * 16384;
            cp16(sA + dA0, a + (size_t)tid * 16);
            cp16(sA + dA1, a + (size_t)(tid + 256) * 16);
            #pragma unroll
            for (int j = 0; j < 4; ++j) cp16(sB + dB[j], b + (size_t)(tid + 256 * j) * 16);
        }
        CP_COMMIT();
    };

    issue_ss(0, 0);
    if (NSC > 1) issue_ss(1, 1);

    int slot = 0;
    for (int i = 0; i < NSC; ++i) {
        if (i + 1 < NSC) CP_WAIT1(); else CP_WAIT0();
        __syncthreads();
        if (i + 2 < NSC) issue_ss(i + 2, (slot + 2) % NSS);

        #pragma unroll
        for (int c = 0; c < 2; ++c) {
            const uint32_t baseA = sb + slot * A_SS + c * 8192;
            const uint32_t baseB = sb + NSS * A_SS + slot * B_SS + c * 16384;
            #pragma unroll
            for (int s = 0; s < 2; ++s) {
                uint32_t ah[2][4], al[2][4], bh[4][2], bl[4][2];
                #pragma unroll
                for (int f = 0; f < 2; ++f) {
                    ldsm4(ah[f], baseA + aoff[0][s][f]);
                    ldsm4(al[f], baseA + aoff[1][s][f]);
                }
                #pragma unroll
                for (int pr = 0; pr < 2; ++pr) {
                    uint32_t t[4];
                    ldsm4(t, baseB + boff[0][s][pr]);
                    bh[2*pr][0]=t[0]; bh[2*pr][1]=t[1]; bh[2*pr+1][0]=t[2]; bh[2*pr+1][1]=t[3];
                    ldsm4(t, baseB + boff[1][s][pr]);
                    bl[2*pr][0]=t[0]; bl[2*pr][1]=t[1]; bl[2*pr+1][0]=t[2]; bl[2*pr+1][1]=t[3];
                }
                #pragma unroll
                for (int f = 0; f < 2; ++f)
                    #pragma unroll
                    for (int j = 0; j < 4; ++j) {
                        mma16816(acc[f][j], ah[f], bh[j]);   // hh
                        mma16816(acc[f][j], al[f], bh[j]);   // lh
                        mma16816(acc[f][j], ah[f], bl[j]);   // hl
                    }
            }
        }
        slot = (slot + 1 == NSS) ? 0 : slot + 1;
    }
    __syncthreads();

    // ---- stage accumulators into smem ----
    float* so = (float*)dsm;                     // 64 x 129
    #pragma unroll
    for (int i2 = 0; i2 < 2; ++i2)
        #pragma unroll
        for (int j = 0; j < 4; ++j)
            #pragma unroll
            for (int r = 0; r < 4; ++r) {
                int row = warp_m * 32 + i2 * 16 + (lane >> 2) + ((r >> 1) << 3);
                int col = warp_n * 32 + j * 8 + ((lane & 3) << 1) + (r & 1);
                so[row * 129 + col] = acc[i2][j][r];
            }
    __syncthreads();

    if (OMODE == 0 || OMODE == 3) {
        float* C = (float*)Cout + (SPLITZ ? (size_t)blockIdx.z * (size_t)kbase : 0);
        #pragma unroll
        for (int it = 0; it < 8; ++it) {
            int idx = tid + 256 * it;
            int row = idx >> 5, q = idx & 31;
            float o[4];
            #pragma unroll
            for (int u = 0; u < 4; ++u) {
                float v = so[row * 129 + q * 4 + u];
                if (BIAS) v += __ldg(bias + n0 + q * 4 + u);
                if (GELU) v = gelu_f(v);
                o[u] = v;
            }
            *(float4*)(C + (size_t)(m0 + row) * ldOut + n0 + q * 4) = *(const float4*)o;
        }
    } else if (OMODE == 1) {
        char* dst = (char*)Cout;
        #pragma unroll
        for (int it = 0; it < 4; ++it) {
            int task = tid + 256 * it;               // 1024 tasks: 64 m x 16 c-groups
            int m = task >> 4, c = (task & 15) * 8;
            float v[8];
            #pragma unroll
            for (int u = 0; u < 8; ++u) {
                float x = so[m * 129 + c + u];
                if (BIAS) x += __ldg(bias + n0 + c + u);
                if (GELU) x = gelu_f(x);
                v[u] = x;
            }
            uint4 hi, lo;
            pack8(v, hi, lo);
            int kk = kbase + n0 + c;
            size_t base = (((size_t)(kk >> 5) * ldOut + m0 + m) << 7) + ((kk & 31) >> 3) * 16;
            *(uint4*)(dst + base) = hi;
            *(uint4*)(dst + base + 64) = lo;
        }
    } else {
        // packed transposed: out rows = n-global, k = m-global
        char* dst = (char*)Cout;
        int h = tid >> 7, n = tid & 127;
        float bv = BIAS ? __ldg(bias + n0 + n) : 0.f;
        float v[32];
        #pragma unroll
        for (int i2 = 0; i2 < 32; ++i2) {
            float x = so[(h * 32 + i2) * 129 + n] + bv;
            if (GELU) x = gelu_f(x);
            v[i2] = x;
        }
        size_t base = (((size_t)((m0 >> 5) + h) * ldOut + n0 + n) << 7);
        #pragma unroll
        for (int q = 0; q < 4; ++q) {
            uint4 hi, lo;
            pack8(v + 8 * q, hi, lo);
            *(uint4*)(dst + base + q * 16) = hi;
            *(uint4*)(dst + base + 64 + q * 16) = lo;
        }
    }
}

// ---------------- generic fp32 -> packed converter (R6 proven) ----------------
__global__ void pack_kernel(const float* __restrict__ src, char* __restrict__ dst,
                            int R, int K, int total) {
    int idx = blockIdx.x * 256 + threadIdx.x;
    if (idx >= total) return;
    int kg = K >> 3;
    int r = idx / kg;
    int koff = (idx - r * kg) << 3;
    float f[8];
    *(float4*)f       = *(const float4*)(src + (size_t)r * K + koff);
    *(float4*)(f + 4) = *(const float4*)(src + (size_t)r * K + koff + 4);
    uint4 hi, lo;
    pack8(f, hi, lo);
    size_t base = (((size_t)(koff >> 5) * R + r) << 7) + ((koff & 31) >> 3) * 16;
    *(uint4*)(dst + base) = hi;
    *(uint4*)(dst + base + 64) = lo;
}

// ---------------- 1) weight net ----------------
__global__ void weight_kernel(const float* __restrict__ w1, const float* __restrict__ b1,
                              const float* __restrict__ w2, const float* __restrict__ b2) {
    int l = threadIdx.x;
    if (l >= NLAG) return;
    float lag = (float)(l - QLAG);
    float acc = b2[0];
    #pragma unroll 8
    for (int j = 0; j < 64; ++j) acc += gelu_f(lag * w1[j] + b1[j]) * w2[j];
    g_w[l] = acc;
}

// ---------------- 2) fused center + FIR + pack: one X-row read ----------------
__global__ void center_fir_kernel(const float* __restrict__ X, char* __restrict__ Zp,
                                  char* __restrict__ Xcp, char* __restrict__ Yp) {
    __shared__ float sbuf[DDIM + 2 * QLAG];
    __shared__ float ws[NLAG];
    __shared__ float red[256];
    int r = blockIdx.x, tid = threadIdx.x;
    if (tid < NLAG) ws[tid] = g_w[tid];
    if (tid < QLAG) { sbuf[tid] = 0.f; sbuf[DDIM + QLAG + tid] = 0.f; }

    const float* xr = X + (size_t)r * DDIM;
    float f0[8], f1[8];
    int k0 = tid * 8, k1 = 2048 + tid * 8;
    *(float4*)f0       = *(const float4*)(xr + k0);
    *(float4*)(f0 + 4) = *(const float4*)(xr + k0 + 4);
    *(float4*)f1       = *(const float4*)(xr + k1);
    *(float4*)(f1 + 4) = *(const float4*)(xr + k1 + 4);
    float s = 0.f;
    #pragma unroll
    for (int u = 0; u < 8; ++u) s += f0[u] + f1[u];
    red[tid] = s; __syncthreads();
    for (int off = 128; off > 0; off >>= 1) {
        if (tid < off) red[tid] += red[tid + off];
        __syncthreads();
    }
    float mean = red[0] * (1.0f / DDIM);

    uint4 hi, lo;
    size_t b0 = (((size_t)(k0 >> 5) * NROWS + r) << 7) + ((k0 & 31) >> 3) * 16;
    size_t b1 = (((size_t)(k1 >> 5) * NROWS + r) << 7) + ((k1 & 31) >> 3) * 16;
    pack8(f0, hi, lo);
    *(uint4*)(Zp + b0) = hi; *(uint4*)(Zp + b0 + 64) = lo;
    pack8(f1, hi, lo);
    *(uint4*)(Zp + b1) = hi; *(uint4*)(Zp + b1 + 64) = lo;

    #pragma unroll
    for (int u = 0; u < 8; ++u) { f0[u] -= mean; f1[u] -= mean; }
    pack8(f0, hi, lo);
    *(uint4*)(Xcp + b0) = hi; *(uint4*)(Xcp + b0 + 64) = lo;
    pack8(f1, hi, lo);
    *(uint4*)(Xcp + b1) = hi; *(uint4*)(Xcp + b1 + 64) = lo;

    *(float4*)(&sbuf[QLAG + k0])     = *(float4*)f0;
    *(float4*)(&sbuf[QLAG + k0 + 4]) = *(float4*)(f0 + 4);
    *(float4*)(&sbuf[QLAG + k1])     = *(float4*)f1;
    *(float4*)(&sbuf[QLAG + k1 + 4]) = *(float4*)(f1 + 4);
    __syncthreads();

    float acc[16];
    #pragma unroll
    for (int q = 0; q < 16; ++q) acc[q] = 0.f;
    for (int i = 0; i < NLAG; ++i) {
        float wv = ws[i];
        #pragma unroll
        for (int q = 0; q < 16; ++q) acc[q] += wv * sbuf[tid + 256 * q + i];
    }
    __syncthreads();
    #pragma unroll
    for (int q = 0; q < 16; ++q) sbuf[tid + 256 * q] = acc[q];
    __syncthreads();

    int t0 = tid * 16;
    float v[16];
    #pragma unroll
    for (int u = 0; u < 16; ++u) v[u] = sbuf[t0 + u];
    #pragma unroll
    for (int g = 0; g < 2; ++g) {
        int koff = t0 + 8 * g;
        size_t base = (((size_t)(koff >> 5) * NROWS + r) << 7) + ((koff & 31) >> 3) * 16;
        pack8(v + 8 * g, hi, lo);
        *(uint4*)(Yp + base) = hi;
        *(uint4*)(Yp + base + 64) = lo;
    }
}

// ---------------- transpose X -> packed Xt [DDIM rows, K=NROWS] ----------------
__global__ void transpose_kernel(const float* __restrict__ X, char* __restrict__ XTp) {
    __shared__ float t[32][33];
    int bx = blockIdx.x * 32;
    int by = blockIdx.y * 32;
    int x = threadIdx.x, y = threadIdx.y;
    #pragma unroll
    for (int j = 0; j < 32; j += 8)
        t[y + j][x] = X[(size_t)(by + y + j) * DDIM + bx + x];
    __syncthreads();
    int tt = y * 32 + x;
    if (tt < 128) {
        int rr = tt >> 2, grp = tt & 3;
        float v[8];
        #pragma unroll
        for (int u = 0; u < 8; ++u) v[u] = t[grp * 8 + u][rr];
        uint4 hi, lo;
        pack8(v, hi, lo);
        size_t base = (((size_t)(by >> 5) * DDIM + bx + rr) << 7) + grp * 16;
        *(uint4*)(XTp + base) = hi;
        *(uint4*)(XTp + base + 64) = lo;
    }
}

// cov reduce + pack: 8192 tasks (256 rows x 32 groups of 8)
__global__ void cov_reduce(char* __restrict__ Cp) {
    int idx = blockIdx.x * 256 + threadIdx.x;
    int r = idx >> 5;
    int cg = (idx & 31) << 3;
    float v[8];
    #pragma unroll
    for (int u = 0; u < 8; ++u) v[u] = 0.f;
    #pragma unroll
    for (int z = 0; z < SPLITK; ++z) {
        const float* p = g_covpart + (size_t)z * NROWS * NROWS + (size_t)r * NROWS + cg;
        float4 a = *(const float4*)p, b = *(const float4*)(p + 4);
        v[0]+=a.x; v[1]+=a.y; v[2]+=a.z; v[3]+=a.w;
        v[4]+=b.x; v[5]+=b.y; v[6]+=b.z; v[7]+=b.w;
    }
    #pragma unroll
    for (int u = 0; u < 8; ++u) v[u] *= (1.0f / DDIM);
    uint4 hi, lo;
    pack8(v, hi, lo);
    size_t base = (((size_t)(cg >> 5) * NROWS + r) << 7) + ((cg & 31) >> 3) * 16;
    *(uint4*)(Cp + base) = hi;
    *(uint4*)(Cp + base + 64) = lo;
}

// ---------------- launch (single stream) ----------------
extern "C" void kernel_launch(void* const* d_in, const int* in_sizes, int n_in,
                              void* d_out, int out_size) {
    const float* X     = (const float*)d_in[0];
    const float* wn_w1 = (const float*)d_in[1];
    const float* wn_b1 = (const float*)d_in[2];
    const float* wn_w2 = (const float*)d_in[3];
    const float* wn_b2 = (const float*)d_in[4];
    const float* fc1_w = (const float*)d_in[5];
    const float* fc1_b = (const float*)d_in[6];
    const float* fc2_w = (const float*)d_in[7];
    const float* fc2_b = (const float*)d_in[8];
    const float* fc3_w = (const float*)d_in[9];
    const float* fc3_b = (const float*)d_in[10];
    const float* proj  = (const float*)d_in[11];
    float* out = (float*)d_out;

    char *pWp1, *pWp2, *pWp3, *pPp, *pZp, *po1p, *po2p, *po3tp, *pXtp, *pCp, *pXcp, *pYp;
    float *pcovp;
    cudaGetSymbolAddress((void**)&pWp1,  g_Wp1);
    cudaGetSymbolAddress((void**)&pWp2,  g_Wp2);
    cudaGetSymbolAddress((void**)&pWp3,  g_Wp3);
    cudaGetSymbolAddress((void**)&pPp,   g_Pp);
    cudaGetSymbolAddress((void**)&pZp,   g_Zp);
    cudaGetSymbolAddress((void**)&po1p,  g_o1p);
    cudaGetSymbolAddress((void**)&po2p,  g_o2p);
    cudaGetSymbolAddress((void**)&po3tp, g_o3tp);
    cudaGetSymbolAddress((void**)&pXtp,  g_Xtp);
    cudaGetSymbolAddress((void**)&pCp,   g_Cp);
    cudaGetSymbolAddress((void**)&pXcp,  g_Xcp);
    cudaGetSymbolAddress((void**)&pYp,   g_Yp);
    cudaGetSymbolAddress((void**)&pcovp, g_covpart);

    cudaFuncSetAttribute(gemm_k<0, false, false, false>, cudaFuncAttributeMaxDynamicSharedMemorySize, GEMM_SMEM);
    cudaFuncSetAttribute(gemm_k<1, false, false, false>, cudaFuncAttributeMaxDynamicSharedMemorySize, GEMM_SMEM);
    cudaFuncSetAttribute(gemm_k<1, true,  true,  false>, cudaFuncAttributeMaxDynamicSharedMemorySize, GEMM_SMEM);
    cudaFuncSetAttribute(gemm_k<2, true,  false, false>, cudaFuncAttributeMaxDynamicSharedMemorySize, GEMM_SMEM);
    cudaFuncSetAttribute(gemm_k<3, false, false, true >, cudaFuncAttributeMaxDynamicSharedMemorySize, GEMM_SMEM);

    weight_kernel<<<1, NLAG>>>(wn_w1, wn_b1, wn_w2, wn_b2);
    center_fir_kernel<<<NROWS, 256>>>(X, pZp, pXcp, pYp);
    transpose_kernel<<<dim3(DDIM / 32, NROWS / 32), dim3(32, 8)>>>(X, pXtp);
    // cov partials: HMMA split-K over blockIdx.z (SPLITK=16 -> 128 CTAs, K-slice = 256 = 8 chunks)
    gemm_k<3, false, false, true><<<dim3(NROWS / 128, NROWS / 64, SPLITK), 256, GEMM_SMEM>>>(
        pXcp, pYp, pcovp, nullptr, (DDIM / SPLITK) / 32, NROWS, NROWS, NROWS, NROWS * NROWS);
    cov_reduce<<<32, 256>>>(pCp);

    // cov_inter = cov @ X -> Zp right half (packed, kbase=DDIM)
    gemm_k<1, false, false, false><<<dim3(DDIM / 128, NROWS / 64), 256, GEMM_SMEM>>>(
        pCp, pXtp, pZp, nullptr, NROWS / 32, NROWS, DDIM, NROWS, DDIM);

    // pack weights + proj
    {
        int t1 = HID * CIN / 8;
        pack_kernel<<<(t1 + 255) / 256, 256>>>(fc1_w, pWp1, HID, CIN, t1);
        int t2 = HID * HID / 8;
        pack_kernel<<<(t2 + 255) / 256, 256>>>(fc2_w, pWp2, HID, HID, t2);
        pack_kernel<<<(t2 + 255) / 256, 256>>>(fc3_w, pWp3, HID, HID, t2);
        int t3 = Y0DIM * NROWS / 8;
        pack_kernel<<<(t3 + 255) / 256, 256>>>(proj, pPp, Y0DIM, NROWS, t3);
    }

    // fc1: gelu(Z @ fc1_w^T + b) -> o1p
    gemm_k<1, true, true, false><<<dim3(HID / 128, NROWS / 64), 256, GEMM_SMEM>>>(
        pZp, pWp1, po1p, fc1_b, CIN / 32, NROWS, HID, NROWS, 0);
    // fc2: gelu(o1 @ fc2_w^T + b) -> o2p
    gemm_k<1, true, true, false><<<dim3(HID / 128, NROWS / 64), 256, GEMM_SMEM>>>(
        po1p, pWp2, po2p, fc2_b, HID / 32, NROWS, HID, NROWS, 0);
    // fc3: o2 @ fc3_w^T + b -> o3tp (packed transposed)
    gemm_k<2, true, false, false><<<dim3(HID / 128, NROWS / 64), 256, GEMM_SMEM>>>(
        po2p, pWp3, po3tp, fc3_b, HID / 32, NROWS, HID, HID, 0);
    // out = proj @ o3 (NT: A=projp, B=o3tp) -> fp32 out
    gemm_k<0, false, false, false><<<dim3(HID / 128, Y0DIM / 64), 256, GEMM_SMEM>>>(
        pPp, po3tp, out, nullptr, NROWS / 32, Y0DIM, HID, HID, 0);
}

// round 15
// speedup vs baseline: 1.0454x; 1.0175x over previous
#include <cuda_runtime.h>
#include <cuda_bf16.h>
#include <math.h>
#include <cstdint>

#define NROWS 256
#define DDIM  4096
#define CIN   8192
#define HID   4096
#define Y0DIM 512
#define QLAG  64
#define NLAG  129
#define SPLITK 16

// ---------------- scratch (device globals; no allocations allowed) ----------------
__device__ float g_w[NLAG];
__device__ float g_covpart[SPLITK * NROWS * NROWS];

// packed operands: per 32-k chunk, per row: 128B = [hi bf16 x32 | lo bf16 x32]
__device__ __align__(128) char g_Wp1[(size_t)HID * CIN * 4];     // fc1_w packed
__device__ __align__(128) char g_Wp2[(size_t)HID * HID * 4];     // fc2_w packed
__device__ __align__(128) char g_Wp3[(size_t)HID * HID * 4];     // fc3_w packed
__device__ __align__(128) char g_Pp [(size_t)Y0DIM * NROWS * 4]; // proj packed
__device__ __align__(128) char g_Zp [(size_t)NROWS * CIN * 4];   // [X | cov@X] packed
__device__ __align__(128) char g_o1p[(size_t)NROWS * HID * 4];
__device__ __align__(128) char g_o2p[(size_t)NROWS * HID * 4];
__device__ __align__(128) char g_o3tp[(size_t)HID * NROWS * 4];  // fc3 out transposed packed
__device__ __align__(128) char g_Xtp[(size_t)DDIM * NROWS * 4];  // X^T packed
__device__ __align__(128) char g_Cp [(size_t)NROWS * NROWS * 4]; // cov packed
__device__ __align__(128) char g_Xcp[(size_t)NROWS * DDIM * 4];  // centered X packed
__device__ __align__(128) char g_Yp [(size_t)NROWS * DDIM * 4];  // FIR output packed

__device__ __forceinline__ float gelu_f(float x) {
    return 0.5f * x * (1.0f + erff(x * 0.70710678118654752440f));
}
__device__ __forceinline__ uint32_t smem_u32(const void* p) {
    uint32_t a;
    asm("{ .reg .u64 t; cvta.to.shared.u64 t, %1; cvt.u32.u64 %0, t; }" : "=r"(a) : "l"(p));
    return a;
}
__device__ __forceinline__ void ldsm4(uint32_t* r, uint32_t addr) {
    asm volatile("ldmatrix.sync.aligned.m8n8.x4.shared.b16 {%0,%1,%2,%3}, [%4];"
        : "=r"(r[0]), "=r"(r[1]), "=r"(r[2]), "=r"(r[3]) : "r"(addr));
}
__device__ __forceinline__ void mma16816(float* c, const uint32_t* a, const uint32_t* b) {
    asm volatile(
        "mma.sync.aligned.m16n8k16.row.col.f32.bf16.bf16.f32 "
        "{%0,%1,%2,%3}, {%4,%5,%6,%7}, {%8,%9}, {%0,%1,%2,%3};"
        : "+f"(c[0]), "+f"(c[1]), "+f"(c[2]), "+f"(c[3])
        : "r"(a[0]), "r"(a[1]), "r"(a[2]), "r"(a[3]), "r"(b[0]), "r"(b[1]));
}
__device__ __forceinline__ uint32_t pack_bf(float a, float b) {
    __nv_bfloat162 t;
    t.x = __float2bfloat16(a);
    t.y = __float2bfloat16(b);
    return *reinterpret_cast<uint32_t*>(&t);
}
__device__ __forceinline__ float bf_hi(float x) {
    return __bfloat162float(__float2bfloat16(x));
}
__device__ __forceinline__ uint32_t swz(uint32_t off) {
    return off ^ (((off >> 7) & 7) << 4);
}
__device__ __forceinline__ void cp16(uint32_t d, const void* s) {
    asm volatile("cp.async.cg.shared.global [%0], [%1], 16;" :: "r"(d), "l"(s) : "memory");
}
#define CP_COMMIT() asm volatile("cp.async.commit_group;" ::: "memory")
#define CP_WAIT1()  asm volatile("cp.async.wait_group 1;" ::: "memory")
#define CP_WAIT0()  asm volatile("cp.async.wait_group 0;" ::: "memory")

// pack 8 fp32 -> hi uint4 (8 bf16) + lo uint4
__device__ __forceinline__ void pack8(const float* f, uint4& hi, uint4& lo) {
    float h[8];
    #pragma unroll
    for (int u = 0; u < 8; ++u) h[u] = bf_hi(f[u]);
    hi = make_uint4(pack_bf(h[0], h[1]), pack_bf(h[2], h[3]),
                    pack_bf(h[4], h[5]), pack_bf(h[6], h[7]));
    lo = make_uint4(pack_bf(f[0]-h[0], f[1]-h[1]), pack_bf(f[2]-h[2], f[3]-h[3]),
                    pack_bf(f[4]-h[4], f[5]-h[5]), pack_bf(f[6]-h[6], f[7]-h[7]));
}

// ====================== pipelined HMMA bf16 3-split NT GEMM (R12/R14 proven) ======================
// Operands pre-packed. BM=64, BN=128. Superstage = 2 chunks (64 k), 3 slots, wait depth 1.
// OMODE: 0 = fp32 row-major out; 1 = packed out (kbase = k offset);
//        2 = packed transposed out; 3 = fp32 out + blockIdx.z partial (kbase = zstride)
#define NSS 3
#define A_SS 16384                       // 2 chunks x 8KB
#define B_SS 32768                       // 2 chunks x 16KB
#define GEMM_SMEM (NSS * (A_SS + B_SS))  // 144KB

template <int OMODE, bool BIAS, bool GELU, bool SPLITZ>
__global__ void __launch_bounds__(256) gemm_k(
    const char* __restrict__ Ap, const char* __restrict__ Bp,
    void* __restrict__ Cout, const float* __restrict__ bias,
    int NC, int RA, int RB, int ldOut, int kbase)
{
    extern __shared__ __align__(128) char dsm[];
    const uint32_t sb = smem_u32(dsm);
    const int tid = threadIdx.x;
    const int lane = tid & 31, wid = tid >> 5;
    const int warp_m = wid >> 2, warp_n = wid & 3;
    const int m0 = blockIdx.y * 64, n0 = blockIdx.x * 128;
    const int zb = SPLITZ ? blockIdx.z * NC : 0;

    const uint32_t dA0 = swz(tid * 16), dA1 = swz((tid + 256) * 16);
    uint32_t dB[4];
    #pragma unroll
    for (int j = 0; j < 4; ++j) dB[j] = swz((tid + 256 * j) * 16);

    // ldmatrix offsets within one 8KB(A)/16KB(B) chunk: [plane][kstep][frag]
    uint32_t aoff[2][2][2], boff[2][2][2];
    #pragma unroll
    for (int p = 0; p < 2; ++p)
        #pragma unroll
        for (int s = 0; s < 2; ++s)
            #pragma unroll
            for (int f = 0; f < 2; ++f) {
                int rowA = warp_m * 32 + f * 16 + (lane & 15);
                aoff[p][s][f] = swz((uint32_t)rowA * 128 + p * 64 + s * 32 + ((lane >> 4) << 4));
                int rowB = warp_n * 32 + f * 16 + (((lane >> 4) & 1) << 3) + (lane & 7);
                boff[p][s][f] = swz((uint32_t)rowB * 128 + p * 64 + s * 32 + (((lane >> 3) & 1) << 4));
            }

    float acc[2][4][4];
    #pragma unroll
    for (int i = 0; i < 2; ++i)
        #pragma unroll
        for (int j = 0; j < 4; ++j)
            #pragma unroll
            for (int r = 0; r < 4; ++r) acc[i][j][r] = 0.f;

    const int NSC = NC >> 1;             // superchunks (NC always even)

    auto issue_ss = [&](int isc, int slot) {
        #pragma unroll
        for (int c = 0; c < 2; ++c) {
            int ic = 2 * isc + c;
            const char* a = Ap + (((size_t)(zb + ic) * RA + m0) << 7);
            const char* b = Bp + (((size_t)(zb + ic) * RB + n0) << 7);
            uint32_t sA = sb + slot * A_SS + c * 8192;
            uint32_t sB = sb + NSS * A_SS + slot * B_SS + c * 16384;
            cp16(sA + dA0, a + (size_t)tid * 16);
            cp16(sA + dA1, a + (size_t)(tid + 256) * 16);
            #pragma unroll
            for (int j = 0; j < 4; ++j) cp16(sB + dB[j], b + (size_t)(tid + 256 * j) * 16);
        }
        CP_COMMIT();
    };

    issue_ss(0, 0);
    if (NSC > 1) issue_ss(1, 1);

    int slot = 0;
    for (int i = 0; i < NSC; ++i) {
        if (i + 1 < NSC) CP_WAIT1(); else CP_WAIT0();
        __syncthreads();
        if (i + 2 < NSC) issue_ss(i + 2, (slot + 2) % NSS);

        #pragma unroll
        for (int c = 0; c < 2; ++c) {
            const uint32_t baseA = sb + slot * A_SS + c * 8192;
            const uint32_t baseB = sb + NSS * A_SS + slot * B_SS + c * 16384;
            #pragma unroll
            for (int s = 0; s < 2; ++s) {
                uint32_t ah[2][4], al[2][4], bh[4][2], bl[4][2];
                #pragma unroll
                for (int f = 0; f < 2; ++f) {
                    ldsm4(ah[f], baseA + aoff[0][s][f]);
                    ldsm4(al[f], baseA + aoff[1][s][f]);
                }
                #pragma unroll
                for (int pr = 0; pr < 2; ++pr) {
                    uint32_t t[4];
                    ldsm4(t, baseB + boff[0][s][pr]);
                    bh[2*pr][0]=t[0]; bh[2*pr][1]=t[1]; bh[2*pr+1][0]=t[2]; bh[2*pr+1][1]=t[3];
                    ldsm4(t, baseB + boff[1][s][pr]);
                    bl[2*pr][0]=t[0]; bl[2*pr][1]=t[1]; bl[2*pr+1][0]=t[2]; bl[2*pr+1][1]=t[3];
                }
                #pragma unroll
                for (int f = 0; f < 2; ++f)
                    #pragma unroll
                    for (int j = 0; j < 4; ++j) {
                        mma16816(acc[f][j], ah[f], bh[j]);   // hh
                        mma16816(acc[f][j], al[f], bh[j]);   // lh
                        mma16816(acc[f][j], ah[f], bl[j]);   // hl
                    }
            }
        }
        slot = (slot + 1 == NSS) ? 0 : slot + 1;
    }
    __syncthreads();

    // ---- stage accumulators into smem ----
    float* so = (float*)dsm;                     // 64 x 129
    #pragma unroll
    for (int i2 = 0; i2 < 2; ++i2)
        #pragma unroll
        for (int j = 0; j < 4; ++j)
            #pragma unroll
            for (int r = 0; r < 4; ++r) {
                int row = warp_m * 32 + i2 * 16 + (lane >> 2) + ((r >> 1) << 3);
                int col = warp_n * 32 + j * 8 + ((lane & 3) << 1) + (r & 1);
                so[row * 129 + col] = acc[i2][j][r];
            }
    __syncthreads();

    if (OMODE == 0 || OMODE == 3) {
        float* C = (float*)Cout + (SPLITZ ? (size_t)blockIdx.z * (size_t)kbase : 0);
        #pragma unroll
        for (int it = 0; it < 8; ++it) {
            int idx = tid + 256 * it;
            int row = idx >> 5, q = idx & 31;
            float o[4];
            #pragma unroll
            for (int u = 0; u < 4; ++u) {
                float v = so[row * 129 + q * 4 + u];
                if (BIAS) v += __ldg(bias + n0 + q * 4 + u);
                if (GELU) v = gelu_f(v);
                o[u] = v;
            }
            *(float4*)(C + (size_t)(m0 + row) * ldOut + n0 + q * 4) = *(const float4*)o;
        }
    } else if (OMODE == 1) {
        char* dst = (char*)Cout;
        #pragma unroll
        for (int it = 0; it < 4; ++it) {
            int task = tid + 256 * it;               // 1024 tasks: 64 m x 16 c-groups
            int m = task >> 4, c = (task & 15) * 8;
            float v[8];
            #pragma unroll
            for (int u = 0; u < 8; ++u) {
                float x = so[m * 129 + c + u];
                if (BIAS) x += __ldg(bias + n0 + c + u);
                if (GELU) x = gelu_f(x);
                v[u] = x;
            }
            uint4 hi, lo;
            pack8(v, hi, lo);
            int kk = kbase + n0 + c;
            size_t base = (((size_t)(kk >> 5) * ldOut + m0 + m) << 7) + ((kk & 31) >> 3) * 16;
            *(uint4*)(dst + base) = hi;
            *(uint4*)(dst + base + 64) = lo;
        }
    } else {
        // packed transposed: out rows = n-global, k = m-global
        char* dst = (char*)Cout;
        int h = tid >> 7, n = tid & 127;
        float bv = BIAS ? __ldg(bias + n0 + n) : 0.f;
        float v[32];
        #pragma unroll
        for (int i2 = 0; i2 < 32; ++i2) {
            float x = so[(h * 32 + i2) * 129 + n] + bv;
            if (GELU) x = gelu_f(x);
            v[i2] = x;
        }
        size_t base = (((size_t)((m0 >> 5) + h) * ldOut + n0 + n) << 7);
        #pragma unroll
        for (int q = 0; q < 4; ++q) {
            uint4 hi, lo;
            pack8(v + 8 * q, hi, lo);
            *(uint4*)(dst + base + q * 16) = hi;
            *(uint4*)(dst + base + 64 + q * 16) = lo;
        }
    }
}

// ---------------- combined fp32 -> packed converter: all 4 weights in ONE launch ----------------
// Segments (in 8-float tasks):
//   [0, T1)          fc1_w: R=HID,   K=CIN
//   [T1, T1+T2)      fc2_w: R=HID,   K=HID
//   [T1+T2, T1+2T2)  fc3_w: R=HID,   K=HID
//   [.., +T3)        proj : R=Y0DIM, K=NROWS
#define T1 (HID * CIN / 8)
#define T2 (HID * HID / 8)
#define T3 (Y0DIM * NROWS / 8)
#define TPACK (T1 + 2 * T2 + T3)

__device__ __forceinline__ void pack_one(const float* __restrict__ src, char* __restrict__ dst,
                                         int R, int K, int idx) {
    int kg = K >> 3;
    int r = idx / kg;
    int koff = (idx - r * kg) << 3;
    float f[8];
    *(float4*)f       = *(const float4*)(src + (size_t)r * K + koff);
    *(float4*)(f + 4) = *(const float4*)(src + (size_t)r * K + koff + 4);
    uint4 hi, lo;
    pack8(f, hi, lo);
    size_t base = (((size_t)(koff >> 5) * R + r) << 7) + ((koff & 31) >> 3) * 16;
    *(uint4*)(dst + base) = hi;
    *(uint4*)(dst + base + 64) = lo;
}

__global__ void pack_all_kernel(const float* __restrict__ w1, const float* __restrict__ w2,
                                const float* __restrict__ w3, const float* __restrict__ pr,
                                char* __restrict__ d1, char* __restrict__ d2,
                                char* __restrict__ d3, char* __restrict__ dp) {
    int idx = blockIdx.x * 256 + threadIdx.x;
    if (idx < T1) {
        pack_one(w1, d1, HID, CIN, idx);
    } else if (idx < T1 + T2) {
        pack_one(w2, d2, HID, HID, idx - T1);
    } else if (idx < T1 + 2 * T2) {
        pack_one(w3, d3, HID, HID, idx - T1 - T2);
    } else if (idx < TPACK) {
        pack_one(pr, dp, Y0DIM, NROWS, idx - T1 - 2 * T2);
    }
}

// ---------------- 1) weight net ----------------
__global__ void weight_kernel(const float* __restrict__ w1, const float* __restrict__ b1,
                              const float* __restrict__ w2, const float* __restrict__ b2) {
    int l = threadIdx.x;
    if (l >= NLAG) return;
    float lag = (float)(l - QLAG);
    float acc = b2[0];
    #pragma unroll 8
    for (int j = 0; j < 64; ++j) acc += gelu_f(lag * w1[j] + b1[j]) * w2[j];
    g_w[l] = acc;
}

// ---------------- 2) fused center + FIR + pack: one X-row read ----------------
__global__ void center_fir_kernel(const float* __restrict__ X, char* __restrict__ Zp,
                                  char* __restrict__ Xcp, char* __restrict__ Yp) {
    __shared__ float sbuf[DDIM + 2 * QLAG];
    __shared__ float ws[NLAG];
    __shared__ float red[256];
    int r = blockIdx.x, tid = threadIdx.x;
    if (tid < NLAG) ws[tid] = g_w[tid];
    if (tid < QLAG) { sbuf[tid] = 0.f; sbuf[DDIM + QLAG + tid] = 0.f; }

    const float* xr = X + (size_t)r * DDIM;
    float f0[8], f1[8];
    int k0 = tid * 8, k1 = 2048 + tid * 8;
    *(float4*)f0       = *(const float4*)(xr + k0);
    *(float4*)(f0 + 4) = *(const float4*)(xr + k0 + 4);
    *(float4*)f1       = *(const float4*)(xr + k1);
    *(float4*)(f1 + 4) = *(const float4*)(xr + k1 + 4);
    float s = 0.f;
    #pragma unroll
    for (int u = 0; u < 8; ++u) s += f0[u] + f1[u];
    red[tid] = s; __syncthreads();
    for (int off = 128; off > 0; off >>= 1) {
        if (tid < off) red[tid] += red[tid + off];
        __syncthreads();
    }
    float mean = red[0] * (1.0f / DDIM);

    uint4 hi, lo;
    size_t b0 = (((size_t)(k0 >> 5) * NROWS + r) << 7) + ((k0 & 31) >> 3) * 16;
    size_t b1 = (((size_t)(k1 >> 5) * NROWS + r) << 7) + ((k1 & 31) >> 3) * 16;
    pack8(f0, hi, lo);
    *(uint4*)(Zp + b0) = hi; *(uint4*)(Zp + b0 + 64) = lo;
    pack8(f1, hi, lo);
    *(uint4*)(Zp + b1) = hi; *(uint4*)(Zp + b1 + 64) = lo;

    #pragma unroll
    for (int u = 0; u < 8; ++u) { f0[u] -= mean; f1[u] -= mean; }
    pack8(f0, hi, lo);
    *(uint4*)(Xcp + b0) = hi; *(uint4*)(Xcp + b0 + 64) = lo;
    pack8(f1, hi, lo);
    *(uint4*)(Xcp + b1) = hi; *(uint4*)(Xcp + b1 + 64) = lo;

    *(float4*)(&sbuf[QLAG + k0])     = *(float4*)f0;
    *(float4*)(&sbuf[QLAG + k0 + 4]) = *(float4*)(f0 + 4);
    *(float4*)(&sbuf[QLAG + k1])     = *(float4*)f1;
    *(float4*)(&sbuf[QLAG + k1 + 4]) = *(float4*)(f1 + 4);
    __syncthreads();

    float acc[16];
    #pragma unroll
    for (int q = 0; q < 16; ++q) acc[q] = 0.f;
    for (int i = 0; i < NLAG; ++i) {
        float wv = ws[i];
        #pragma unroll
        for (int q = 0; q < 16; ++q) acc[q] += wv * sbuf[tid + 256 * q + i];
    }
    __syncthreads();
    #pragma unroll
    for (int q = 0; q < 16; ++q) sbuf[tid + 256 * q] = acc[q];
    __syncthreads();

    int t0 = tid * 16;
    float v[16];
    #pragma unroll
    for (int u = 0; u < 16; ++u) v[u] = sbuf[t0 + u];
    #pragma unroll
    for (int g = 0; g < 2; ++g) {
        int koff = t0 + 8 * g;
        size_t base = (((size_t)(koff >> 5) * NROWS + r) << 7) + ((koff & 31) >> 3) * 16;
        pack8(v + 8 * g, hi, lo);
        *(uint4*)(Yp + base) = hi;
        *(uint4*)(Yp + base + 64) = lo;
    }
}

// ---------------- transpose X -> packed Xt [DDIM rows, K=NROWS] ----------------
__global__ void transpose_kernel(const float* __restrict__ X, char* __restrict__ XTp) {
    __shared__ float t[32][33];
    int bx = blockIdx.x * 32;
    int by = blockIdx.y * 32;
    int x = threadIdx.x, y = threadIdx.y;
    #pragma unroll
    for (int j = 0; j < 32; j += 8)
        t[y + j][x] = X[(size_t)(by + y + j) * DDIM + bx + x];
    __syncthreads();
    int tt = y * 32 + x;
    if (tt < 128) {
        int rr = tt >> 2, grp = tt & 3;
        float v[8];
        #pragma unroll
        for (int u = 0; u < 8; ++u) v[u] = t[grp * 8 + u][rr];
        uint4 hi, lo;
        pack8(v, hi, lo);
        size_t base = (((size_t)(by >> 5) * DDIM + bx + rr) << 7) + grp * 16;
        *(uint4*)(XTp + base) = hi;
        *(uint4*)(XTp + base + 64) = lo;
    }
}

// cov reduce + pack: 8192 tasks (256 rows x 32 groups of 8)
__global__ void cov_reduce(char* __restrict__ Cp) {
    int idx = blockIdx.x * 256 + threadIdx.x;
    int r = idx >> 5;
    int cg = (idx & 31) << 3;
    float v[8];
    #pragma unroll
    for (int u = 0; u < 8; ++u) v[u] = 0.f;
    #pragma unroll
    for (int z = 0; z < SPLITK; ++z) {
        const float* p = g_covpart + (size_t)z * NROWS * NROWS + (size_t)r * NROWS + cg;
        float4 a = *(const float4*)p, b = *(const float4*)(p + 4);
        v[0]+=a.x; v[1]+=a.y; v[2]+=a.z; v[3]+=a.w;
        v[4]+=b.x; v[5]+=b.y; v[6]+=b.z; v[7]+=b.w;
    }
    #pragma unroll
    for (int u = 0; u < 8; ++u) v[u] *= (1.0f / DDIM);
    uint4 hi, lo;
    pack8(v, hi, lo);
    size_t base = (((size_t)(cg >> 5) * NROWS + r) << 7) + ((cg & 31) >> 3) * 16;
    *(uint4*)(Cp + base) = hi;
    *(uint4*)(Cp + base + 64) = lo;
}

// ---------------- launch (single stream) ----------------
extern "C" void kernel_launch(void* const* d_in, const int* in_sizes, int n_in,
                              void* d_out, int out_size) {
    const float* X     = (const float*)d_in[0];
    const float* wn_w1 = (const float*)d_in[1];
    const float* wn_b1 = (const float*)d_in[2];
    const float* wn_w2 = (const float*)d_in[3];
    const float* wn_b2 = (const float*)d_in[4];
    const float* fc1_w = (const float*)d_in[5];
    const float* fc1_b = (const float*)d_in[6];
    const float* fc2_w = (const float*)d_in[7];
    const float* fc2_b = (const float*)d_in[8];
    const float* fc3_w = (const float*)d_in[9];
    const float* fc3_b = (const float*)d_in[10];
    const float* proj  = (const float*)d_in[11];
    float* out = (float*)d_out;

    char *pWp1, *pWp2, *pWp3, *pPp, *pZp, *po1p, *po2p, *po3tp, *pXtp, *pCp, *pXcp, *pYp;
    float *pcovp;
    cudaGetSymbolAddress((void**)&pWp1,  g_Wp1);
    cudaGetSymbolAddress((void**)&pWp2,  g_Wp2);
    cudaGetSymbolAddress((void**)&pWp3,  g_Wp3);
    cudaGetSymbolAddress((void**)&pPp,   g_Pp);
    cudaGetSymbolAddress((void**)&pZp,   g_Zp);
    cudaGetSymbolAddress((void**)&po1p,  g_o1p);
    cudaGetSymbolAddress((void**)&po2p,  g_o2p);
    cudaGetSymbolAddress((void**)&po3tp, g_o3tp);
    cudaGetSymbolAddress((void**)&pXtp,  g_Xtp);
    cudaGetSymbolAddress((void**)&pCp,   g_Cp);
    cudaGetSymbolAddress((void**)&pXcp,  g_Xcp);
    cudaGetSymbolAddress((void**)&pYp,   g_Yp);
    cudaGetSymbolAddress((void**)&pcovp, g_covpart);

    cudaFuncSetAttribute(gemm_k<0, false, false, false>, cudaFuncAttributeMaxDynamicSharedMemorySize, GEMM_SMEM);
    cudaFuncSetAttribute(gemm_k<1, false, false, false>, cudaFuncAttributeMaxDynamicSharedMemorySize, GEMM_SMEM);
    cudaFuncSetAttribute(gemm_k<1, true,  true,  false>, cudaFuncAttributeMaxDynamicSharedMemorySize, GEMM_SMEM);
    cudaFuncSetAttribute(gemm_k<2, true,  false, false>, cudaFuncAttributeMaxDynamicSharedMemorySize, GEMM_SMEM);
    cudaFuncSetAttribute(gemm_k<3, false, false, true >, cudaFuncAttributeMaxDynamicSharedMemorySize, GEMM_SMEM);

    weight_kernel<<<1, NLAG>>>(wn_w1, wn_b1, wn_w2, wn_b2);
    center_fir_kernel<<<NROWS, 256>>>(X, pZp, pXcp, pYp);
    transpose_kernel<<<dim3(DDIM / 32, NROWS / 32), dim3(32, 8)>>>(X, pXtp);
    // cov partials: HMMA split-K over blockIdx.z (SPLITK=16 -> 128 CTAs, K-slice = 256 = 8 chunks)
    gemm_k<3, false, false, true><<<dim3(NROWS / 128, NROWS / 64, SPLITK), 256, GEMM_SMEM>>>(
        pXcp, pYp, pcovp, nullptr, (DDIM / SPLITK) / 32, NROWS, NROWS, NROWS, NROWS * NROWS);
    cov_reduce<<<32, 256>>>(pCp);

    // cov_inter = cov @ X -> Zp right half (packed, kbase=DDIM)
    gemm_k<1, false, false, false><<<dim3(DDIM / 128, NROWS / 64), 256, GEMM_SMEM>>>(
        pCp, pXtp, pZp, nullptr, NROWS / 32, NROWS, DDIM, NROWS, DDIM);

    // pack all weights + proj in ONE launch
    pack_all_kernel<<<(TPACK + 255) / 256, 256>>>(fc1_w, fc2_w, fc3_w, proj,
                                                  pWp1, pWp2, pWp3, pPp);

    // fc1: gelu(Z @ fc1_w^T + b) -> o1p
    gemm_k<1, true, true, false><<<dim3(HID / 128, NROWS / 64), 256, GEMM_SMEM>>>(
        pZp, pWp1, po1p, fc1_b, CIN / 32, NROWS, HID, NROWS, 0);
    // fc2: gelu(o1 @ fc2_w^T + b) -> o2p
    gemm_k<1, true, true, false><<<dim3(HID / 128, NROWS / 64), 256, GEMM_SMEM>>>(
        po1p, pWp2, po2p, fc2_b, HID / 32, NROWS, HID, NROWS, 0);
    // fc3: o2 @ fc3_w^T + b -> o3tp (packed transposed)
    gemm_k<2, true, false, false><<<dim3(HID / 128, NROWS / 64), 256, GEMM_SMEM>>>(
        po2p, pWp3, po3tp, fc3_b, HID / 32, NROWS, HID, HID, 0);
    // out = proj @ o3 (NT: A=projp, B=o3tp) -> fp32 out
    gemm_k<0, false, false, false><<<dim3(HID / 128, Y0DIM / 64), 256, GEMM_SMEM>>>(
        pPp, po3tp, out, nullptr, NROWS / 32, Y0DIM, HID, HID, 0);
}